// round 6
// baseline (speedup 1.0000x reference)
#include <cuda_runtime.h>

#define NT 512
#define PA 194            // pitch for A, Q, K, V (even -> 8B aligned pairs)
#define PS 65             // S pitch
#define PW 30             // W stage pitch (24-col chunks; conflict-free LDS.64)

#define OFF_A   0         // 64 x PA : X/Y, then per-head O, then relu(M)
#define OFF_Q   12416     // 64 x PA : scaled Q (persists), then merge2 out T
#define OFF_K   24832     // 64 x PA : full K (per branch)
#define OFF_V   37248     // 64 x PA : full V (per branch)
#define OFF_S   49664     // 64 x PS  (also W stage buffer 1 during GEMM phases)
#define OFF_W0  53824     // 96 x PW = 2880 : W stage buffer 0
#define OFF_W1  OFF_S
#define SMEM_FLOATS 56704 // 226816 bytes

typedef unsigned long long u64;

static __device__ __forceinline__ u64 pk2(float lo, float hi) {
    u64 r; asm("mov.b64 %0,{%1,%2};" : "=l"(r) : "f"(lo), "f"(hi)); return r;
}
static __device__ __forceinline__ void upk2(u64 v, float& lo, float& hi) {
    asm("mov.b64 {%0,%1}, %2;" : "=f"(lo), "=f"(hi) : "l"(v));
}
static __device__ __forceinline__ void fma2(u64& d, u64 a, u64 b) {
    asm("fma.rn.f32x2 %0, %1, %2, %0;" : "+l"(d) : "l"(a), "l"(b));
}

__device__ float g_bias[2 * 6 * 64 * 64];

__global__ void bias_pre_kernel(const float* __restrict__ rpb_x,
                                const float* __restrict__ rpb_y,
                                const int* __restrict__ rel_idx) {
    int i = blockIdx.x * blockDim.x + threadIdx.x;
    if (i >= 2 * 6 * 4096) return;
    int br = i / (6 * 4096);
    int h  = (i / 4096) % 6;
    int nm = i & 4095;
    const float* tab = br ? rpb_y : rpb_x;
    g_bias[i] = tab[rel_idx[nm] * 6 + h];
}

// 64x192 GEMM: dst[n][o] = sum_c src[n][c] * W[o][c] (+bias)*scl.
// Double-buffered 24-col W chunks, register prefetch, 1 sync per chunk.
// DST: 0 -> SMEM (pitch PA), 1 -> global (pitch 192), 2 -> accumulate into M.
template<int DST>
static __device__ __forceinline__ void wide_gemm(
    float* sm, int srcOff, const float* __restrict__ Wg, int ldw,
    const float* __restrict__ bg, float scl,
    float* dstS, float* __restrict__ dstG, float (*M)[6], int t)
{
    const int tr = t >> 5, tc = t & 31, n0 = tr * 4;
    int wbase[5], soff[5];
    bool wok[5];
    #pragma unroll
    for (int k = 0; k < 5; ++k) {
        int e = k * NT + t;
        wok[k] = e < 2304;               // 96 rows x 24 cols
        int jj = e / 24, dd = e - jj * 24;
        wbase[k] = jj * ldw + dd;
        soff[k]  = jj * PW + dd;
    }
    #pragma unroll 1
    for (int half = 0; half < 2; ++half) {
        const float* Wh = Wg + (size_t)half * 96 * ldw;
        u64 acc[4][3];
        #pragma unroll
        for (int i = 0; i < 4; ++i) { acc[i][0] = 0; acc[i][1] = 0; acc[i][2] = 0; }

        float pre[5];
        #pragma unroll
        for (int k = 0; k < 5; ++k) pre[k] = wok[k] ? Wh[wbase[k]] : 0.f;
        #pragma unroll
        for (int k = 0; k < 5; ++k) if (wok[k]) sm[OFF_W0 + soff[k]] = pre[k];
        __syncthreads();

        #pragma unroll 1
        for (int ch = 0; ch < 8; ++ch) {
            if (ch < 7) {
                #pragma unroll
                for (int k = 0; k < 5; ++k)
                    pre[k] = wok[k] ? Wh[wbase[k] + (ch + 1) * 24] : 0.f;
            }
            const float* sa = sm + srcOff + ch * 24;
            const float* wb = sm + ((ch & 1) ? OFF_W1 : OFF_W0);
            #pragma unroll
            for (int dp = 0; dp < 12; ++dp) {
                u64 a2[4], w2[3];
                #pragma unroll
                for (int i = 0; i < 4; ++i)
                    a2[i] = *reinterpret_cast<const u64*>(&sa[(n0 + i) * PA + 2 * dp]);
                #pragma unroll
                for (int j = 0; j < 3; ++j)
                    w2[j] = *reinterpret_cast<const u64*>(&wb[(tc * 3 + j) * PW + 2 * dp]);
                #pragma unroll
                for (int i = 0; i < 4; ++i)
                    #pragma unroll
                    for (int j = 0; j < 3; ++j)
                        fma2(acc[i][j], a2[i], w2[j]);
            }
            if (ch < 7) {
                float* nb = sm + ((ch & 1) ? OFF_W0 : OFF_W1);
                #pragma unroll
                for (int k = 0; k < 5; ++k) if (wok[k]) nb[soff[k]] = pre[k];
            }
            __syncthreads();
        }

        #pragma unroll
        for (int j = 0; j < 3; ++j) {
            const int o = half * 96 + tc * 3 + j;
            #pragma unroll
            for (int i = 0; i < 4; ++i) {
                float lo, hi; upk2(acc[i][j], lo, hi);
                if (DST == 2) {
                    M[i][half * 3 + j] += lo + hi;
                } else {
                    float v = (lo + hi + bg[o]) * scl;
                    if (DST == 1) dstG[(n0 + i) * 192 + o] = v;
                    else          dstS[(n0 + i) * PA + o] = v;
                }
            }
        }
    }
}

__global__ void __launch_bounds__(NT, 1) fused_attn_kernel(
    const float* __restrict__ x, const float* __restrict__ y,
    const float* __restrict__ mask_x, const float* __restrict__ mask_y,
    const float* __restrict__ qkv_w, const float* __restrict__ qkv_b,
    const float* __restrict__ kv_w, const float* __restrict__ kv_b,
    const float* __restrict__ merge1_w, const float* __restrict__ merge1_b,
    const float* __restrict__ merge2_w, const float* __restrict__ merge2_b,
    const float* __restrict__ proj_w, const float* __restrict__ proj_b,
    float* __restrict__ out)
{
    extern __shared__ float sm[];
    const int t = threadIdx.x;
    const int w = blockIdx.x;
    const int tr = t >> 5, tc = t & 31;
    const int n0 = tr * 4;
    const float scale = 0.17677669529663687f;  // 32^-0.5

    // merge1 accumulator in registers; col = half*96 + tc*3 + j, rows n0..n0+3
    float M[4][6];
    #pragma unroll
    for (int half = 0; half < 2; ++half)
        #pragma unroll
        for (int j = 0; j < 3; ++j) {
            float b = merge1_b[half * 96 + tc * 3 + j];
            #pragma unroll
            for (int i = 0; i < 4; ++i) M[i][half * 3 + j] = b;
        }

    #pragma unroll 1
    for (int br = 0; br < 2; ++br) {
        // ---- load activation (X or Y) into A ----
        {
            const float* ap = (br ? y : x) + (size_t)w * 12288;
            for (int i = t; i < 12288; i += NT) {
                int n = i / 192, c = i - n * 192;
                sm[OFF_A + n * PA + c] = ap[i];
            }
        }
        // wide_gemm's first internal sync orders the A stores before reads.
        if (br == 0) {
            wide_gemm<0>(sm, OFF_A, qkv_w,              192, qkv_b,       scale, sm + OFF_Q, nullptr, nullptr, t);
            wide_gemm<0>(sm, OFF_A, qkv_w + 192 * 192,  192, qkv_b + 192, 1.f,   sm + OFF_K, nullptr, nullptr, t);
            wide_gemm<0>(sm, OFF_A, qkv_w + 384 * 192,  192, qkv_b + 384, 1.f,   sm + OFF_V, nullptr, nullptr, t);
        } else {
            wide_gemm<0>(sm, OFF_A, kv_w,               192, kv_b,        1.f,   sm + OFF_K, nullptr, nullptr, t);
            wide_gemm<0>(sm, OFF_A, kv_w + 192 * 192,   192, kv_b + 192,  1.f,   sm + OFF_V, nullptr, nullptr, t);
        }
        __syncthreads();   // Q/K/V epilogue stores -> visible to attention

        const float* bias_base = g_bias + (size_t)(br * 6) * 4096;
        const float* maskp = (br ? mask_y : mask_x) + (size_t)(w & 1023) * 4096;

        // mask is head-invariant: load once per branch (S-phase mapping)
        const int m0 = tc * 2;
        float mk[4][2];
        #pragma unroll
        for (int i = 0; i < 4; ++i)
            #pragma unroll
            for (int j = 0; j < 2; ++j)
                mk[i][j] = maskp[(n0 + i) * 64 + m0 + j];

        #pragma unroll 1
        for (int h = 0; h < 6; ++h) {
            const int h32 = h * 32;

            // ---- S = Q K^T + bias + mask  (4x2 tiles, fma2 over d) ----
            {
                float bi[4][2];
                const float* bb = bias_base + h * 4096;
                #pragma unroll
                for (int i = 0; i < 4; ++i)
                    #pragma unroll
                    for (int j = 0; j < 2; ++j)
                        bi[i][j] = bb[(n0 + i) * 64 + m0 + j];
                u64 acc[4][2];
                #pragma unroll
                for (int i = 0; i < 4; ++i) { acc[i][0] = 0; acc[i][1] = 0; }
                #pragma unroll
                for (int dp = 0; dp < 16; ++dp) {
                    u64 q2[4], k2[2];
                    #pragma unroll
                    for (int i = 0; i < 4; ++i)
                        q2[i] = *reinterpret_cast<const u64*>(
                            &sm[OFF_Q + (n0 + i) * PA + h32 + 2 * dp]);
                    #pragma unroll
                    for (int j = 0; j < 2; ++j)
                        k2[j] = *reinterpret_cast<const u64*>(
                            &sm[OFF_K + (m0 + j) * PA + h32 + 2 * dp]);
                    #pragma unroll
                    for (int i = 0; i < 4; ++i)
                        #pragma unroll
                        for (int j = 0; j < 2; ++j)
                            fma2(acc[i][j], q2[i], k2[j]);
                }
                #pragma unroll
                for (int i = 0; i < 4; ++i)
                    #pragma unroll
                    for (int j = 0; j < 2; ++j) {
                        float lo, hi; upk2(acc[i][j], lo, hi);
                        sm[OFF_S + (n0 + i) * PS + m0 + j] = lo + hi + bi[i][j] + mk[i][j];
                    }
            }
            __syncthreads();

            // ---- softmax per row (16 warps x 4 rows) ----
            {
                const int wi = t >> 5, l = t & 31;
                #pragma unroll
                for (int rr = 0; rr < 4; rr++) {
                    int r = wi * 4 + rr;
                    float v0 = sm[OFF_S + r * PS + l];
                    float v1 = sm[OFF_S + r * PS + 32 + l];
                    float mx = fmaxf(v0, v1);
                    #pragma unroll
                    for (int o = 16; o > 0; o >>= 1)
                        mx = fmaxf(mx, __shfl_xor_sync(0xffffffffu, mx, o));
                    float e0 = __expf(v0 - mx), e1 = __expf(v1 - mx);
                    float s = e0 + e1;
                    #pragma unroll
                    for (int o = 16; o > 0; o >>= 1)
                        s += __shfl_xor_sync(0xffffffffu, s, o);
                    float inv = 1.0f / s;
                    sm[OFF_S + r * PS + l]      = e0 * inv;
                    sm[OFF_S + r * PS + 32 + l] = e1 * inv;
                }
            }
            __syncthreads();

            // ---- O_h = P V_h  -> A region at col h*32 (A is dead) ----
            {
                const int n0p = (t >> 4) * 2, d0 = (t & 15) * 2;
                u64 acc[2];
                acc[0] = 0; acc[1] = 0;
                #pragma unroll 4
                for (int m = 0; m < 64; ++m) {
                    u64 v2 = *reinterpret_cast<const u64*>(
                        &sm[OFF_V + m * PA + h32 + d0]);
                    #pragma unroll
                    for (int i = 0; i < 2; ++i) {
                        float p = sm[OFF_S + (n0p + i) * PS + m];
                        fma2(acc[i], pk2(p, p), v2);
                    }
                }
                #pragma unroll
                for (int i = 0; i < 2; ++i)
                    *reinterpret_cast<u64*>(&sm[OFF_A + (n0p + i) * PA + h32 + d0]) = acc[i];
            }
            __syncthreads();
        }  // heads

        // ---- merge1: M += O_all @ W1_branch^T  (one wide GEMM, red=192) ----
        wide_gemm<2>(sm, OFF_A, merge1_w + br * 192, 384, nullptr, 1.f,
                     nullptr, nullptr, M, t);
        // ends with a full barrier -> safe to overwrite A next branch
    }  // branches

    // ---- leaky relu(M) -> A (dead) ----
    #pragma unroll
    for (int half = 0; half < 2; ++half)
        #pragma unroll
        for (int j = 0; j < 3; ++j)
            #pragma unroll
            for (int i = 0; i < 4; ++i) {
                float v = M[i][half * 3 + j];
                v = v > 0.f ? v : 0.2f * v;
                sm[OFF_A + (n0 + i) * PA + half * 96 + tc * 3 + j] = v;
            }
    // merge2: T = relu(M) @ W2^T + b2 -> Q region
    wide_gemm<0>(sm, OFF_A, merge2_w, 192, merge2_b, 1.f, sm + OFF_Q, nullptr, nullptr, t);
    // proj: out = T @ Wp^T + pb -> global
    wide_gemm<1>(sm, OFF_Q, proj_w, 192, proj_b, 1.f, nullptr,
                 out + (size_t)w * 12288, nullptr, t);
}

extern "C" void kernel_launch(void* const* d_in, const int* in_sizes, int n_in,
                              void* d_out, int out_size) {
    const float* x        = (const float*)d_in[0];
    const float* y        = (const float*)d_in[1];
    const float* mask_x   = (const float*)d_in[2];
    const float* mask_y   = (const float*)d_in[3];
    const float* qkv_w    = (const float*)d_in[4];
    const float* qkv_b    = (const float*)d_in[5];
    const float* kv_w     = (const float*)d_in[6];
    const float* kv_b     = (const float*)d_in[7];
    const float* rpb_x    = (const float*)d_in[8];
    const float* rpb_y    = (const float*)d_in[9];
    const float* merge1_w = (const float*)d_in[10];
    const float* merge1_b = (const float*)d_in[11];
    const float* merge2_w = (const float*)d_in[12];
    const float* merge2_b = (const float*)d_in[13];
    const float* proj_w   = (const float*)d_in[14];
    const float* proj_b   = (const float*)d_in[15];
    const int*   rel_idx  = (const int*)d_in[16];
    float* out = (float*)d_out;

    cudaFuncSetAttribute(fused_attn_kernel,
                         cudaFuncAttributeMaxDynamicSharedMemorySize,
                         SMEM_FLOATS * 4);

    bias_pre_kernel<<<192, 256>>>(rpb_x, rpb_y, rel_idx);
    fused_attn_kernel<<<2048, NT, SMEM_FLOATS * 4>>>(
        x, y, mask_x, mask_y, qkv_w, qkv_b, kv_w, kv_b,
        merge1_w, merge1_b, merge2_w, merge2_b, proj_w, proj_b, out);
}

// round 7
// speedup vs baseline: 1.1260x; 1.1260x over previous
#include <cuda_runtime.h>

#define NT 256
#define PA 196            // pitch for A, Q, V (mult of 4 -> LDS.128 rows)
#define PKT 68            // Kt pitch [d][m]
#define PS 66             // S pitch
#define PW 30             // W stage pitch

#define OFF_A   0         // 64 x PA : X/Y, then per-head O, then relu(M)
#define OFF_Q   12544     // 64 x PA : scaled Q (persists), then merge2 out T
#define OFF_KT  25088     // 192 x PKT : K transposed (per branch)
#define OFF_V   38144     // 64 x PA : full V (per branch)
#define OFF_S   50688     // 64 x PS (also W1 stage buffer during GEMMs)
#define OFF_W0  54912     // 96 x PW = 2880
#define OFF_W1  OFF_S
#define SMEM_FLOATS 57792 // 231168 bytes

typedef unsigned long long u64;
typedef union { float4 f; u64 u[2]; } v4u;

static __device__ __forceinline__ u64 pk2(float lo, float hi) {
    u64 r; asm("mov.b64 %0,{%1,%2};" : "=l"(r) : "f"(lo), "f"(hi)); return r;
}
static __device__ __forceinline__ void upk2(u64 v, float& lo, float& hi) {
    asm("mov.b64 {%0,%1}, %2;" : "=f"(lo), "=f"(hi) : "l"(v));
}
static __device__ __forceinline__ void fma2(u64& d, u64 a, u64 b) {
    asm("fma.rn.f32x2 %0, %1, %2, %0;" : "+l"(d) : "l"(a), "l"(b));
}

__device__ float g_bias[2 * 6 * 64 * 64];

__global__ void bias_pre_kernel(const float* __restrict__ rpb_x,
                                const float* __restrict__ rpb_y,
                                const int* __restrict__ rel_idx) {
    int i = blockIdx.x * blockDim.x + threadIdx.x;
    if (i >= 2 * 6 * 4096) return;
    int br = i / (6 * 4096);
    int h  = (i / 4096) % 6;
    int nm = i & 4095;
    const float* tab = br ? rpb_y : rpb_x;
    g_bias[i] = tab[rel_idx[nm] * 6 + h];
}

// 64x192 GEMM: dst[n][o] = (sum_c src[n][c]*W[o][c] + bias)*scl.
// Double-buffered 24-col W chunks, register prefetch, 1 sync per chunk.
// A loads are LDS.128 warp-broadcasts; W loads LDS.64.
// DST: 0 -> SMEM pitch PA, 1 -> global, 2 -> accumulate into M regs,
//      3 -> SMEM transposed (Kt[o][n], pitch PKT).
template<int DST>
static __device__ __forceinline__ void wide_gemm(
    float* sm, int srcOff, const float* __restrict__ Wg, int ldw,
    const float* __restrict__ bg, float scl,
    float* dstS, float* __restrict__ dstG, float (*M)[6], int t)
{
    const int tr = t >> 5, tc = t & 31, n0 = tr * 8;
    int wbase[9], soff[9];
    #pragma unroll
    for (int k = 0; k < 9; ++k) {
        int e = k * NT + t;
        int jj = e / 24, dd = e - jj * 24;
        wbase[k] = jj * ldw + dd;
        soff[k]  = jj * PW + dd;
    }
    #pragma unroll 1
    for (int half = 0; half < 2; ++half) {
        const float* Wh = Wg + (size_t)half * 96 * ldw;
        u64 acc[8][3];
        #pragma unroll
        for (int i = 0; i < 8; ++i) { acc[i][0] = 0; acc[i][1] = 0; acc[i][2] = 0; }

        float pre[9];
        #pragma unroll
        for (int k = 0; k < 9; ++k) pre[k] = Wh[wbase[k]];
        #pragma unroll
        for (int k = 0; k < 9; ++k) sm[OFF_W0 + soff[k]] = pre[k];
        __syncthreads();

        #pragma unroll 1
        for (int ch = 0; ch < 8; ++ch) {
            if (ch < 7) {
                #pragma unroll
                for (int k = 0; k < 9; ++k) pre[k] = Wh[wbase[k] + (ch + 1) * 24];
            }
            const float* sa = sm + srcOff + ch * 24;
            const float* wb = sm + ((ch & 1) ? OFF_W1 : OFF_W0);
            #pragma unroll
            for (int st = 0; st < 6; ++st) {      // 6 x 4-float steps = 24 cols
                v4u a4[8];
                u64 w2[3][2];
                #pragma unroll
                for (int i = 0; i < 8; ++i)
                    a4[i].f = *reinterpret_cast<const float4*>(
                        &sa[(n0 + i) * PA + 4 * st]);
                #pragma unroll
                for (int j = 0; j < 3; ++j) {
                    w2[j][0] = *reinterpret_cast<const u64*>(
                        &wb[(tc * 3 + j) * PW + 4 * st]);
                    w2[j][1] = *reinterpret_cast<const u64*>(
                        &wb[(tc * 3 + j) * PW + 4 * st + 2]);
                }
                #pragma unroll
                for (int i = 0; i < 8; ++i)
                    #pragma unroll
                    for (int j = 0; j < 3; ++j) {
                        fma2(acc[i][j], a4[i].u[0], w2[j][0]);
                        fma2(acc[i][j], a4[i].u[1], w2[j][1]);
                    }
            }
            if (ch < 7) {
                float* nb = sm + ((ch & 1) ? OFF_W0 : OFF_W1);
                #pragma unroll
                for (int k = 0; k < 9; ++k) nb[soff[k]] = pre[k];
            }
            __syncthreads();
        }

        #pragma unroll
        for (int j = 0; j < 3; ++j) {
            const int o = half * 96 + tc * 3 + j;
            #pragma unroll
            for (int i = 0; i < 8; ++i) {
                float lo, hi; upk2(acc[i][j], lo, hi);
                if (DST == 2) {
                    M[i][half * 3 + j] += lo + hi;
                } else {
                    float v = (lo + hi + bg[o]) * scl;
                    if (DST == 1)      dstG[(n0 + i) * 192 + o] = v;
                    else if (DST == 3) dstS[o * PKT + n0 + i]   = v;
                    else               dstS[(n0 + i) * PA + o]  = v;
                }
            }
        }
    }
}

__global__ void __launch_bounds__(NT, 1) fused_attn_kernel(
    const float* __restrict__ x, const float* __restrict__ y,
    const float* __restrict__ mask_x, const float* __restrict__ mask_y,
    const float* __restrict__ qkv_w, const float* __restrict__ qkv_b,
    const float* __restrict__ kv_w, const float* __restrict__ kv_b,
    const float* __restrict__ merge1_w, const float* __restrict__ merge1_b,
    const float* __restrict__ merge2_w, const float* __restrict__ merge2_b,
    const float* __restrict__ proj_w, const float* __restrict__ proj_b,
    float* __restrict__ out)
{
    extern __shared__ float sm[];
    const int t = threadIdx.x;
    const int w = blockIdx.x;
    const int tr = t >> 5, tc = t & 31;
    const int n0 = tr * 8;
    const float scale = 0.17677669529663687f;  // 32^-0.5

    // merge1 accumulator in registers; col = half*96 + tc*3 + j, rows n0..n0+7
    float M[8][6];
    #pragma unroll
    for (int half = 0; half < 2; ++half)
        #pragma unroll
        for (int j = 0; j < 3; ++j) {
            float b = merge1_b[half * 96 + tc * 3 + j];
            #pragma unroll
            for (int i = 0; i < 8; ++i) M[i][half * 3 + j] = b;
        }

    // attention-phase mappings (warp-local: warp wi owns rows 8wi..8wi+7)
    const int sr0 = (t >> 4) * 4;           // S: 4 rows
    const int sm0 = (t & 15) * 4;           // S: 4 m-cols
    const int pvrow = (t >> 5) * 8 + ((t & 31) >> 2);  // PV: 1 row
    const int pvd0  = (t & 3) * 8;                     // PV: 8 d-cols

    #pragma unroll 1
    for (int br = 0; br < 2; ++br) {
        // ---- load activation (X or Y) into A ----
        {
            const float* ap = (br ? y : x) + (size_t)w * 12288;
            for (int i = t; i < 12288; i += NT) {
                int n = i / 192, c = i - n * 192;
                sm[OFF_A + n * PA + c] = ap[i];
            }
        }
        // wide_gemm's first internal sync orders the A stores before reads.
        if (br == 0) {
            wide_gemm<0>(sm, OFF_A, qkv_w,             192, qkv_b,       scale, sm + OFF_Q,  nullptr, nullptr, t);
            wide_gemm<3>(sm, OFF_A, qkv_w + 192 * 192, 192, qkv_b + 192, 1.f,   sm + OFF_KT, nullptr, nullptr, t);
            wide_gemm<0>(sm, OFF_A, qkv_w + 384 * 192, 192, qkv_b + 384, 1.f,   sm + OFF_V,  nullptr, nullptr, t);
        } else {
            wide_gemm<3>(sm, OFF_A, kv_w,              192, kv_b,        1.f,   sm + OFF_KT, nullptr, nullptr, t);
            wide_gemm<0>(sm, OFF_A, kv_w + 192 * 192,  192, kv_b + 192,  1.f,   sm + OFF_V,  nullptr, nullptr, t);
        }
        __syncthreads();   // Q/Kt/V epilogue stores -> visible to attention

        const float* bias_base = g_bias + (size_t)(br * 6) * 4096;
        const float* maskp = (br ? mask_y : mask_x) + (size_t)(w & 1023) * 4096;

        // mask is head-invariant: hoist (S mapping)
        float4 mk4[4];
        #pragma unroll
        for (int i = 0; i < 4; ++i)
            mk4[i] = *reinterpret_cast<const float4*>(&maskp[(sr0 + i) * 64 + sm0]);

        #pragma unroll 1
        for (int h = 0; h < 6; ++h) {
            const int h32 = h * 32;

            // ---- S = Q Kt + bias + mask  (4 rows x 2 m-pairs, fma2 over m) ----
            {
                float4 bi4[4];
                const float* bb = bias_base + h * 4096;
                #pragma unroll
                for (int i = 0; i < 4; ++i)
                    bi4[i] = *reinterpret_cast<const float4*>(&bb[(sr0 + i) * 64 + sm0]);
                u64 acc[4][2];
                #pragma unroll
                for (int i = 0; i < 4; ++i) { acc[i][0] = 0; acc[i][1] = 0; }
                #pragma unroll 8
                for (int d = 0; d < 32; ++d) {
                    v4u kt;
                    kt.f = *reinterpret_cast<const float4*>(
                        &sm[OFF_KT + (h32 + d) * PKT + sm0]);
                    #pragma unroll
                    for (int i = 0; i < 4; ++i) {
                        float q = sm[OFF_Q + (sr0 + i) * PA + h32 + d];
                        u64 qq = pk2(q, q);
                        fma2(acc[i][0], qq, kt.u[0]);
                        fma2(acc[i][1], qq, kt.u[1]);
                    }
                }
                #pragma unroll
                for (int i = 0; i < 4; ++i) {
                    float s0, s1, s2, s3;
                    upk2(acc[i][0], s0, s1); upk2(acc[i][1], s2, s3);
                    s0 += bi4[i].x + mk4[i].x;  s1 += bi4[i].y + mk4[i].y;
                    s2 += bi4[i].z + mk4[i].z;  s3 += bi4[i].w + mk4[i].w;
                    *reinterpret_cast<u64*>(&sm[OFF_S + (sr0 + i) * PS + sm0])     = pk2(s0, s1);
                    *reinterpret_cast<u64*>(&sm[OFF_S + (sr0 + i) * PS + sm0 + 2]) = pk2(s2, s3);
                }
            }
            __syncwarp();

            // ---- softmax: warp wi owns rows 8wi..8wi+7 ----
            {
                const int wi = t >> 5, l = t & 31;
                #pragma unroll
                for (int rr = 0; rr < 8; rr++) {
                    int r = wi * 8 + rr;
                    float v0 = sm[OFF_S + r * PS + l];
                    float v1 = sm[OFF_S + r * PS + 32 + l];
                    float mx = fmaxf(v0, v1);
                    #pragma unroll
                    for (int o = 16; o > 0; o >>= 1)
                        mx = fmaxf(mx, __shfl_xor_sync(0xffffffffu, mx, o));
                    float e0 = __expf(v0 - mx), e1 = __expf(v1 - mx);
                    float s = e0 + e1;
                    #pragma unroll
                    for (int o = 16; o > 0; o >>= 1)
                        s += __shfl_xor_sync(0xffffffffu, s, o);
                    float inv = 1.0f / s;
                    sm[OFF_S + r * PS + l]      = e0 * inv;
                    sm[OFF_S + r * PS + 32 + l] = e1 * inv;
                }
            }
            __syncwarp();

            // ---- O = P V  (warp-local P rows) -> A region at col h32 ----
            {
                u64 acc[4];
                #pragma unroll
                for (int i = 0; i < 4; ++i) acc[i] = 0;
                #pragma unroll 4
                for (int m = 0; m < 64; ++m) {
                    float p = sm[OFF_S + pvrow * PS + m];
                    u64 pp = pk2(p, p);
                    v4u v0, v1;
                    v0.f = *reinterpret_cast<const float4*>(
                        &sm[OFF_V + m * PA + h32 + pvd0]);
                    v1.f = *reinterpret_cast<const float4*>(
                        &sm[OFF_V + m * PA + h32 + pvd0 + 4]);
                    fma2(acc[0], pp, v0.u[0]); fma2(acc[1], pp, v0.u[1]);
                    fma2(acc[2], pp, v1.u[0]); fma2(acc[3], pp, v1.u[1]);
                }
                #pragma unroll
                for (int i = 0; i < 4; ++i)
                    *reinterpret_cast<u64*>(
                        &sm[OFF_A + pvrow * PA + h32 + pvd0 + 2 * i]) = acc[i];
            }
            __syncwarp();   // own S rows reusable next head
        }  // heads

        __syncthreads();    // all warps' O complete before merge1 reads A

        // ---- merge1: M += O_all @ W1_branch^T (one wide GEMM, red=192) ----
        wide_gemm<2>(sm, OFF_A, merge1_w + br * 192, 384, nullptr, 1.f,
                     nullptr, nullptr, M, t);
        // ends with a full barrier (last chunk sync) -> safe to overwrite A
    }  // branches

    // ---- leaky relu(M) -> A (dead) ----
    #pragma unroll
    for (int half = 0; half < 2; ++half)
        #pragma unroll
        for (int j = 0; j < 3; ++j)
            #pragma unroll
            for (int i = 0; i < 8; ++i) {
                float v = M[i][half * 3 + j];
                v = v > 0.f ? v : 0.2f * v;
                sm[OFF_A + (n0 + i) * PA + half * 96 + tc * 3 + j] = v;
            }
    // merge2: T = relu(M) @ W2^T + b2 -> Q region
    wide_gemm<0>(sm, OFF_A, merge2_w, 192, merge2_b, 1.f, sm + OFF_Q, nullptr, nullptr, t);
    // proj: out = T @ Wp^T + pb -> global
    wide_gemm<1>(sm, OFF_Q, proj_w, 192, proj_b, 1.f, nullptr,
                 out + (size_t)w * 12288, nullptr, t);
}

extern "C" void kernel_launch(void* const* d_in, const int* in_sizes, int n_in,
                              void* d_out, int out_size) {
    const float* x        = (const float*)d_in[0];
    const float* y        = (const float*)d_in[1];
    const float* mask_x   = (const float*)d_in[2];
    const float* mask_y   = (const float*)d_in[3];
    const float* qkv_w    = (const float*)d_in[4];
    const float* qkv_b    = (const float*)d_in[5];
    const float* kv_w     = (const float*)d_in[6];
    const float* kv_b     = (const float*)d_in[7];
    const float* rpb_x    = (const float*)d_in[8];
    const float* rpb_y    = (const float*)d_in[9];
    const float* merge1_w = (const float*)d_in[10];
    const float* merge1_b = (const float*)d_in[11];
    const float* merge2_w = (const float*)d_in[12];
    const float* merge2_b = (const float*)d_in[13];
    const float* proj_w   = (const float*)d_in[14];
    const float* proj_b   = (const float*)d_in[15];
    const int*   rel_idx  = (const int*)d_in[16];
    float* out = (float*)d_out;

    cudaFuncSetAttribute(fused_attn_kernel,
                         cudaFuncAttributeMaxDynamicSharedMemorySize,
                         SMEM_FLOATS * 4);

    bias_pre_kernel<<<192, 256>>>(rpb_x, rpb_y, rel_idx);
    fused_attn_kernel<<<2048, NT, SMEM_FLOATS * 4>>>(
        x, y, mask_x, mask_y, qkv_w, qkv_b, kv_w, kv_b,
        merge1_w, merge1_b, merge2_w, merge2_b, proj_w, proj_b, out);
}

// round 8
// speedup vs baseline: 1.1298x; 1.0034x over previous
#include <cuda_runtime.h>

#define NT 256
#define PA 196            // pitch for A, Q, V (mult of 4 -> LDS.128 rows)
#define PKT 68            // Kt pitch [d][m]
#define PS 66             // S pitch
#define PW 30             // W stage pitch

#define OFF_A   0         // 64 x PA : X/Y, then per-head O, then relu(M)
#define OFF_Q   12544     // 64 x PA : scaled Q (persists), then merge2 out T
#define OFF_KT  25088     // 192 x PKT : K transposed (per branch)
#define OFF_V   38144     // 64 x PA : full V (per branch)
#define OFF_S   50688     // 64 x PS (also W1 stage buffer during GEMMs)
#define OFF_W0  54912     // 96 x PW = 2880
#define OFF_W1  OFF_S
#define SMEM_FLOATS 57792 // 231168 bytes

typedef unsigned long long u64;
typedef union { float4 f; u64 u[2]; } v4u;

static __device__ __forceinline__ u64 pk2(float lo, float hi) {
    u64 r; asm("mov.b64 %0,{%1,%2};" : "=l"(r) : "f"(lo), "f"(hi)); return r;
}
static __device__ __forceinline__ void upk2(u64 v, float& lo, float& hi) {
    asm("mov.b64 {%0,%1}, %2;" : "=f"(lo), "=f"(hi) : "l"(v));
}
static __device__ __forceinline__ void fma2(u64& d, u64 a, u64 b) {
    asm("fma.rn.f32x2 %0, %1, %2, %0;" : "+l"(d) : "l"(a), "l"(b));
}

__device__ float g_bias[2 * 6 * 64 * 64];

__global__ void bias_pre_kernel(const float* __restrict__ rpb_x,
                                const float* __restrict__ rpb_y,
                                const int* __restrict__ rel_idx) {
    int i = blockIdx.x * blockDim.x + threadIdx.x;
    if (i >= 2 * 6 * 4096) return;
    int br = i / (6 * 4096);
    int h  = (i / 4096) % 6;
    int nm = i & 4095;
    const float* tab = br ? rpb_y : rpb_x;
    g_bias[i] = tab[rel_idx[nm] * 6 + h];
}

// 64x192 GEMM: dst[n][o] = (sum_c src[n][c]*W[o][c] + bias)*scl.
// Double-buffered 24-col W chunks, register prefetch, 1 sync per chunk.
// A loads are LDS.128 warp-broadcasts; W loads LDS.64.
// DST: 0 -> SMEM pitch PA, 1 -> global, 2 -> accumulate into M regs,
//      3 -> SMEM transposed (Kt[o][n], pitch PKT).
template<int DST>
static __device__ __forceinline__ void wide_gemm(
    float* sm, int srcOff, const float* __restrict__ Wg, int ldw,
    const float* __restrict__ bg, float scl,
    float* dstS, float* __restrict__ dstG, float (*M)[6], int t)
{
    const int tr = t >> 5, tc = t & 31, n0 = tr * 8;
    int wbase[9], soff[9];
    #pragma unroll
    for (int k = 0; k < 9; ++k) {
        int e = k * NT + t;
        int jj = e / 24, dd = e - jj * 24;
        wbase[k] = jj * ldw + dd;
        soff[k]  = jj * PW + dd;
    }
    #pragma unroll 1
    for (int half = 0; half < 2; ++half) {
        const float* Wh = Wg + (size_t)half * 96 * ldw;
        u64 acc[8][3];
        #pragma unroll
        for (int i = 0; i < 8; ++i) { acc[i][0] = 0; acc[i][1] = 0; acc[i][2] = 0; }

        float pre[9];
        #pragma unroll
        for (int k = 0; k < 9; ++k) pre[k] = Wh[wbase[k]];
        #pragma unroll
        for (int k = 0; k < 9; ++k) sm[OFF_W0 + soff[k]] = pre[k];
        __syncthreads();

        #pragma unroll 1
        for (int ch = 0; ch < 8; ++ch) {
            if (ch < 7) {
                #pragma unroll
                for (int k = 0; k < 9; ++k) pre[k] = Wh[wbase[k] + (ch + 1) * 24];
            }
            const float* sa = sm + srcOff + ch * 24;
            const float* wb = sm + ((ch & 1) ? OFF_W1 : OFF_W0);
            #pragma unroll
            for (int st = 0; st < 6; ++st) {      // 6 x 4-float steps = 24 cols
                v4u a4[8];
                u64 w2[3][2];
                #pragma unroll
                for (int i = 0; i < 8; ++i)
                    a4[i].f = *reinterpret_cast<const float4*>(
                        &sa[(n0 + i) * PA + 4 * st]);
                #pragma unroll
                for (int j = 0; j < 3; ++j) {
                    w2[j][0] = *reinterpret_cast<const u64*>(
                        &wb[(tc * 3 + j) * PW + 4 * st]);
                    w2[j][1] = *reinterpret_cast<const u64*>(
                        &wb[(tc * 3 + j) * PW + 4 * st + 2]);
                }
                #pragma unroll
                for (int i = 0; i < 8; ++i)
                    #pragma unroll
                    for (int j = 0; j < 3; ++j) {
                        fma2(acc[i][j], a4[i].u[0], w2[j][0]);
                        fma2(acc[i][j], a4[i].u[1], w2[j][1]);
                    }
            }
            if (ch < 7) {
                float* nb = sm + ((ch & 1) ? OFF_W0 : OFF_W1);
                #pragma unroll
                for (int k = 0; k < 9; ++k) nb[soff[k]] = pre[k];
            }
            __syncthreads();
        }

        #pragma unroll
        for (int j = 0; j < 3; ++j) {
            const int o = half * 96 + tc * 3 + j;
            #pragma unroll
            for (int i = 0; i < 8; ++i) {
                float lo, hi; upk2(acc[i][j], lo, hi);
                if (DST == 2) {
                    M[i][half * 3 + j] += lo + hi;
                } else {
                    float v = (lo + hi + bg[o]) * scl;
                    if (DST == 1)      dstG[(n0 + i) * 192 + o] = v;
                    else if (DST == 3) dstS[o * PKT + n0 + i]   = v;
                    else               dstS[(n0 + i) * PA + o]  = v;
                }
            }
        }
    }
}

__global__ void __launch_bounds__(NT, 1) fused_attn_kernel(
    const float* __restrict__ x, const float* __restrict__ y,
    const float* __restrict__ mask_x, const float* __restrict__ mask_y,
    const float* __restrict__ qkv_w, const float* __restrict__ qkv_b,
    const float* __restrict__ kv_w, const float* __restrict__ kv_b,
    const float* __restrict__ merge1_w, const float* __restrict__ merge1_b,
    const float* __restrict__ merge2_w, const float* __restrict__ merge2_b,
    const float* __restrict__ proj_w, const float* __restrict__ proj_b,
    float* __restrict__ out)
{
    extern __shared__ float sm[];
    const int t = threadIdx.x;
    const int w = blockIdx.x;
    const int tr = t >> 5, tc = t & 31;
    const int n0 = tr * 8;
    const float scale = 0.17677669529663687f;  // 32^-0.5

    // merge1 accumulator in registers; col = half*96 + tc*3 + j, rows n0..n0+7
    float M[8][6];
    #pragma unroll
    for (int half = 0; half < 2; ++half)
        #pragma unroll
        for (int j = 0; j < 3; ++j) {
            float b = merge1_b[half * 96 + tc * 3 + j];
            #pragma unroll
            for (int i = 0; i < 8; ++i) M[i][half * 3 + j] = b;
        }

    // attention-phase mappings (warp-local: warp wi owns rows 8wi..8wi+7)
    const int sr0 = (t >> 4) * 4;           // S: 4 rows
    const int sm0 = (t & 15) * 4;           // S: 4 m-cols
    const int pvrow = (t >> 5) * 8 + ((t & 31) >> 2);  // PV: 1 row
    const int pvd0  = (t & 3) * 8;                     // PV: 8 d-cols

    #pragma unroll 1
    for (int br = 0; br < 2; ++br) {
        // ---- load activation (X or Y) into A ----
        {
            const float* ap = (br ? y : x) + (size_t)w * 12288;
            for (int i = t; i < 12288; i += NT) {
                int n = i / 192, c = i - n * 192;
                sm[OFF_A + n * PA + c] = ap[i];
            }
        }
        // wide_gemm's first internal sync orders the A stores before reads.
        if (br == 0) {
            wide_gemm<0>(sm, OFF_A, qkv_w,             192, qkv_b,       scale, sm + OFF_Q,  nullptr, nullptr, t);
            wide_gemm<3>(sm, OFF_A, qkv_w + 192 * 192, 192, qkv_b + 192, 1.f,   sm + OFF_KT, nullptr, nullptr, t);
            wide_gemm<0>(sm, OFF_A, qkv_w + 384 * 192, 192, qkv_b + 384, 1.f,   sm + OFF_V,  nullptr, nullptr, t);
        } else {
            wide_gemm<3>(sm, OFF_A, kv_w,              192, kv_b,        1.f,   sm + OFF_KT, nullptr, nullptr, t);
            wide_gemm<0>(sm, OFF_A, kv_w + 192 * 192,  192, kv_b + 192,  1.f,   sm + OFF_V,  nullptr, nullptr, t);
        }
        __syncthreads();   // Q/Kt/V epilogue stores -> visible to attention

        const float* bias_base = g_bias + (size_t)(br * 6) * 4096;
        const float* maskp = (br ? mask_y : mask_x) + (size_t)(w & 1023) * 4096;

        // mask is head-invariant: hoist (S mapping)
        float4 mk4[4];
        #pragma unroll
        for (int i = 0; i < 4; ++i)
            mk4[i] = *reinterpret_cast<const float4*>(&maskp[(sr0 + i) * 64 + sm0]);

        #pragma unroll 1
        for (int h = 0; h < 6; ++h) {
            const int h32 = h * 32;

            // ---- S = Q Kt + bias + mask  (4 rows x 2 m-pairs, fma2 over m) ----
            {
                float4 bi4[4];
                const float* bb = bias_base + h * 4096;
                #pragma unroll
                for (int i = 0; i < 4; ++i)
                    bi4[i] = *reinterpret_cast<const float4*>(&bb[(sr0 + i) * 64 + sm0]);
                u64 acc[4][2];
                #pragma unroll
                for (int i = 0; i < 4; ++i) { acc[i][0] = 0; acc[i][1] = 0; }
                #pragma unroll 8
                for (int d = 0; d < 32; ++d) {
                    v4u kt;
                    kt.f = *reinterpret_cast<const float4*>(
                        &sm[OFF_KT + (h32 + d) * PKT + sm0]);
                    #pragma unroll
                    for (int i = 0; i < 4; ++i) {
                        float q = sm[OFF_Q + (sr0 + i) * PA + h32 + d];
                        u64 qq = pk2(q, q);
                        fma2(acc[i][0], qq, kt.u[0]);
                        fma2(acc[i][1], qq, kt.u[1]);
                    }
                }
                #pragma unroll
                for (int i = 0; i < 4; ++i) {
                    float s0, s1, s2, s3;
                    upk2(acc[i][0], s0, s1); upk2(acc[i][1], s2, s3);
                    s0 += bi4[i].x + mk4[i].x;  s1 += bi4[i].y + mk4[i].y;
                    s2 += bi4[i].z + mk4[i].z;  s3 += bi4[i].w + mk4[i].w;
                    *reinterpret_cast<u64*>(&sm[OFF_S + (sr0 + i) * PS + sm0])     = pk2(s0, s1);
                    *reinterpret_cast<u64*>(&sm[OFF_S + (sr0 + i) * PS + sm0 + 2]) = pk2(s2, s3);
                }
            }
            __syncwarp();

            // ---- softmax: warp wi owns rows 8wi..8wi+7 ----
            {
                const int wi = t >> 5, l = t & 31;
                #pragma unroll
                for (int rr = 0; rr < 8; rr++) {
                    int r = wi * 8 + rr;
                    float v0 = sm[OFF_S + r * PS + l];
                    float v1 = sm[OFF_S + r * PS + 32 + l];
                    float mx = fmaxf(v0, v1);
                    #pragma unroll
                    for (int o = 16; o > 0; o >>= 1)
                        mx = fmaxf(mx, __shfl_xor_sync(0xffffffffu, mx, o));
                    float e0 = __expf(v0 - mx), e1 = __expf(v1 - mx);
                    float s = e0 + e1;
                    #pragma unroll
                    for (int o = 16; o > 0; o >>= 1)
                        s += __shfl_xor_sync(0xffffffffu, s, o);
                    float inv = 1.0f / s;
                    sm[OFF_S + r * PS + l]      = e0 * inv;
                    sm[OFF_S + r * PS + 32 + l] = e1 * inv;
                }
            }
            __syncwarp();

            // ---- O = P V  (warp-local P rows) -> A region at col h32 ----
            {
                u64 acc[4];
                #pragma unroll
                for (int i = 0; i < 4; ++i) acc[i] = 0;
                #pragma unroll 4
                for (int m = 0; m < 64; ++m) {
                    float p = sm[OFF_S + pvrow * PS + m];
                    u64 pp = pk2(p, p);
                    v4u v0, v1;
                    v0.f = *reinterpret_cast<const float4*>(
                        &sm[OFF_V + m * PA + h32 + pvd0]);
                    v1.f = *reinterpret_cast<const float4*>(
                        &sm[OFF_V + m * PA + h32 + pvd0 + 4]);
                    fma2(acc[0], pp, v0.u[0]); fma2(acc[1], pp, v0.u[1]);
                    fma2(acc[2], pp, v1.u[0]); fma2(acc[3], pp, v1.u[1]);
                }
                #pragma unroll
                for (int i = 0; i < 4; ++i)
                    *reinterpret_cast<u64*>(
                        &sm[OFF_A + pvrow * PA + h32 + pvd0 + 2 * i]) = acc[i];
            }
            __syncwarp();   // own S rows reusable next head
        }  // heads

        __syncthreads();    // all warps' O complete before merge1 reads A

        // ---- merge1: M += O_all @ W1_branch^T (one wide GEMM, red=192) ----
        wide_gemm<2>(sm, OFF_A, merge1_w + br * 192, 384, nullptr, 1.f,
                     nullptr, nullptr, M, t);
        // ends with a full barrier (last chunk sync) -> safe to overwrite A
    }  // branches

    // ---- leaky relu(M) -> A (dead) ----
    #pragma unroll
    for (int half = 0; half < 2; ++half)
        #pragma unroll
        for (int j = 0; j < 3; ++j)
            #pragma unroll
            for (int i = 0; i < 8; ++i) {
                float v = M[i][half * 3 + j];
                v = v > 0.f ? v : 0.2f * v;
                sm[OFF_A + (n0 + i) * PA + half * 96 + tc * 3 + j] = v;
            }
    // merge2: T = relu(M) @ W2^T + b2 -> Q region
    wide_gemm<0>(sm, OFF_A, merge2_w, 192, merge2_b, 1.f, sm + OFF_Q, nullptr, nullptr, t);
    // proj: out = T @ Wp^T + pb -> global
    wide_gemm<1>(sm, OFF_Q, proj_w, 192, proj_b, 1.f, nullptr,
                 out + (size_t)w * 12288, nullptr, t);
}

extern "C" void kernel_launch(void* const* d_in, const int* in_sizes, int n_in,
                              void* d_out, int out_size) {
    const float* x        = (const float*)d_in[0];
    const float* y        = (const float*)d_in[1];
    const float* mask_x   = (const float*)d_in[2];
    const float* mask_y   = (const float*)d_in[3];
    const float* qkv_w    = (const float*)d_in[4];
    const float* qkv_b    = (const float*)d_in[5];
    const float* kv_w     = (const float*)d_in[6];
    const float* kv_b     = (const float*)d_in[7];
    const float* rpb_x    = (const float*)d_in[8];
    const float* rpb_y    = (const float*)d_in[9];
    const float* merge1_w = (const float*)d_in[10];
    const float* merge1_b = (const float*)d_in[11];
    const float* merge2_w = (const float*)d_in[12];
    const float* merge2_b = (const float*)d_in[13];
    const float* proj_w   = (const float*)d_in[14];
    const float* proj_b   = (const float*)d_in[15];
    const int*   rel_idx  = (const int*)d_in[16];
    float* out = (float*)d_out;

    cudaFuncSetAttribute(fused_attn_kernel,
                         cudaFuncAttributeMaxDynamicSharedMemorySize,
                         SMEM_FLOATS * 4);

    bias_pre_kernel<<<192, 256>>>(rpb_x, rpb_y, rel_idx);
    fused_attn_kernel<<<2048, NT, SMEM_FLOATS * 4>>>(
        x, y, mask_x, mask_y, qkv_w, qkv_b, kv_w, kv_b,
        merge1_w, merge1_b, merge2_w, merge2_b, proj_w, proj_b, out);
}